// round 16
// baseline (speedup 1.0000x reference)
#include <cuda_runtime.h>
#include <cuda_bf16.h>
#include <math.h>
#include <stdint.h>

#define PP   10000
#define UU   8000
#define DD   64
#define BBATCH 4096
#define NGNZ 320000
#define NDNZ 320000
#define NUNZ 400000
#define NPUNZ 400000
#define PPAD 10112            // 79 * 128

#define OUT_BATCH 0
#define OUT_FUS   (BBATCH*DD)
#define OUT_LOSS  (OUT_FUS + PP*DD)

#define CNT_ALL_N (4*PP + UU)

// ---------------- scratch (static device memory) ---------------------------------
__device__ float g_Ggeo[PP*DD], g_Gseq[PP*DD], g_Colg[PP*DD];
__device__ float g_T1[PP*DD], g_T3[PP*DD], g_T4[PP*DD];
__device__ float g_NGb[PP*DD], g_NSb[PP*DD];
__device__ __nv_bfloat16 g_NGhi[PPAD*DD], g_NShi[PPAD*DD];
__device__ float g_MG[UU*DD], g_MS[UU*DD], g_MP[UU*DD], g_HU[UU*DD], g_US[UU*DD];
__device__ float g_rowsum[PP], g_colsum[PP];
__device__ int   g_cnt_all[CNT_ALL_N], g_cur_all[CNT_ALL_N];
__device__ int   g_ptr_geo[PP+1], g_ptr_src[PP+1], g_ptr_tar[PP+1], g_ptr_pu[PP+1], g_ptr_up[UU+1];
__device__ int2  g_cs_geo[NGNZ], g_cs_src[NDNZ], g_cs_tar[NDNZ], g_cs_up[NUNZ], g_cs_pu[NPUNZ];

// ---------------- fast exp via MUFU.EX2 (SFU pipe, frees FMA pipe) -----------------
__device__ __forceinline__ float fexp_logit(float x) {    // exp(x/T) = exp(5x)
    float y = x * 7.2134752044448169f;                    // 5 * log2(e)
    float r;
    asm("ex2.approx.f32 %0, %1;" : "=f"(r) : "f"(y));
    return r;
}

// ---------------- warp-MMA helpers (portable PTX: no tcgen05) ----------------------
__device__ __forceinline__ uint32_t smem_u32(const void* p) {
    uint32_t a;
    asm("{ .reg .u64 t; cvta.to.shared.u64 t, %1; cvt.u32.u64 %0, t; }" : "=r"(a) : "l"(p));
    return a;
}
__device__ __forceinline__ void ldm4(uint32_t* r, uint32_t addr) {
    asm volatile("ldmatrix.sync.aligned.m8n8.x4.shared.b16 {%0,%1,%2,%3}, [%4];"
                 : "=r"(r[0]), "=r"(r[1]), "=r"(r[2]), "=r"(r[3]) : "r"(addr));
}
__device__ __forceinline__ void mma16816(float* d, const uint32_t* a, uint32_t b0, uint32_t b1) {
    asm volatile("mma.sync.aligned.m16n8k16.row.col.f32.bf16.bf16.f32 "
                 "{%0,%1,%2,%3}, {%4,%5,%6,%7}, {%8,%9}, {%0,%1,%2,%3};"
                 : "+f"(d[0]), "+f"(d[1]), "+f"(d[2]), "+f"(d[3])
                 : "r"(a[0]), "r"(a[1]), "r"(a[2]), "r"(a[3]), "r"(b0), "r"(b1));
}

// ---------------- CSR build --------------------------------------------------------
__global__ void zero_main_kernel(int* cnt_all) {
    int i = blockIdx.x * 256 + threadIdx.x;
    if (i < 2 * PP) cnt_all[PP + i] = 0;     // src @ [PP,2PP), tar @ [2PP,3PP)
}
__global__ void zero_aux_kernel(int* cnt_all, float* rowsum, float* colsum, float* lossp) {
    int i = blockIdx.x * 256 + threadIdx.x;
    if (i < PP) cnt_all[i] = 0;                              // geo
    if (i < PP + UU) cnt_all[3 * PP + i] = 0;                // up + pu
    if (i < PP) { rowsum[i] = 0.f; colsum[i] = 0.f; }
    if (i == 0) lossp[0] = 0.f;
}

// ILP-8 histograms (latency-bound: 8 concurrent atomic chains per thread)
__global__ void hist2_kernel(const int* tar, const int* src, int* cnt_all) {
    int m = blockIdx.y;
    const int* rows = m ? src : tar;
    int base = m ? PP : 2 * PP;
    int i0 = blockIdx.x * 2048 + threadIdx.x;
    #pragma unroll
    for (int k = 0; k < 8; k++) {
        int i = i0 + k * 256;
        if (i < NDNZ) atomicAdd(&cnt_all[base + rows[i]], 1);
    }
}
__global__ void hist3_kernel(const int* geo, const int* up, const int* pu, int* cnt_all) {
    int m = blockIdx.y;
    const int* rows; int base, nnz;
    if (m == 0)      { rows = geo; base = 0;          nnz = NGNZ; }
    else if (m == 1) { rows = up;  base = 3*PP;       nnz = NUNZ; }
    else             { rows = pu;  base = 3*PP + UU;  nnz = NPUNZ; }
    int i0 = blockIdx.x * 2048 + threadIdx.x;
    #pragma unroll
    for (int k = 0; k < 8; k++) {
        int i = i0 + k * 256;
        if (i < nnz) atomicAdd(&cnt_all[base + rows[i]], 1);
    }
}

// single-block scan over one segment, 8 elements/thread (8192 per sweep)
__device__ __forceinline__ void scan_seg(const int* __restrict__ cnt, int* __restrict__ ptr,
                                         int* __restrict__ cur, int n) {
    __shared__ int wsum[32];
    __shared__ int carry;
    int t = threadIdx.x, lane = t & 31, w = t >> 5;
    if (t == 0) { carry = 0; ptr[0] = 0; }
    __syncthreads();
    for (int c0 = 0; c0 < n; c0 += 8192) {
        int idx = c0 + 8 * t;
        int v[8];
        #pragma unroll
        for (int j = 0; j < 8; j++)
            v[j] = (idx + j < n) ? cnt[idx + j] : 0;
        int s = 0;
        #pragma unroll
        for (int j = 0; j < 8; j++) s += v[j];
        #pragma unroll
        for (int off = 1; off < 32; off <<= 1) {
            int y = __shfl_up_sync(0xffffffffu, s, off);
            if (lane >= off) s += y;
        }
        if (lane == 31) wsum[w] = s;
        __syncthreads();
        if (w == 0) {
            int ws = wsum[lane];
            #pragma unroll
            for (int off = 1; off < 32; off <<= 1) {
                int y = __shfl_up_sync(0xffffffffu, ws, off);
                if (lane >= off) ws += y;
            }
            wsum[lane] = ws;
        }
        __syncthreads();
        int add = carry + (w ? wsum[w - 1] : 0);
        int incl[8];
        incl[7] = s + add;
        #pragma unroll
        for (int j = 6; j >= 0; j--) incl[j] = incl[j + 1] - v[j + 1];
        #pragma unroll
        for (int j = 0; j < 8; j++) {
            if (idx + j < n) {
                ptr[idx + j + 1] = incl[j];
                cur[idx + j] = incl[j] - v[j];
            }
        }
        __syncthreads();
        if (t == 0) carry += wsum[31];
        __syncthreads();
    }
}
__global__ void scan2_kernel(const int* cnt_all, int* cur_all, int* ptr_tar, int* ptr_src) {
    if (blockIdx.x == 0) scan_seg(cnt_all + 2*PP, ptr_tar, cur_all + 2*PP, PP);
    else                 scan_seg(cnt_all + PP,   ptr_src, cur_all + PP,   PP);
}
__global__ void scan3_kernel(const int* cnt_all, int* cur_all,
                             int* ptr_geo, int* ptr_up, int* ptr_pu) {
    if (blockIdx.x == 0)      scan_seg(cnt_all,              ptr_geo, cur_all,              PP);
    else if (blockIdx.x == 1) scan_seg(cnt_all + 3*PP,       ptr_up,  cur_all + 3*PP,       UU);
    else                      scan_seg(cnt_all + 3*PP + UU,  ptr_pu,  cur_all + 3*PP + UU,  PP);
}

// ILP-8 scatters
__global__ void scatter2_kernel(const int* tr, const int* tc, const float* tv,
                                const int* sr, const int* sc, const float* sv,
                                int2* cs_tar, int2* cs_src, int* cur_all) {
    int m = blockIdx.y;
    const int* rows = m ? sr : tr;
    const int* cols = m ? sc : tc;
    const float* vals = m ? sv : tv;
    int2* cs = m ? cs_src : cs_tar;
    int* cur = cur_all + (m ? PP : 2 * PP);
    int i0 = blockIdx.x * 2048 + threadIdx.x;
    #pragma unroll
    for (int k = 0; k < 8; k++) {
        int i = i0 + k * 256;
        if (i < NDNZ) {
            int p = atomicAdd(&cur[rows[i]], 1);
            cs[p] = make_int2(cols[i], __float_as_int(vals[i]));
        }
    }
}
__global__ void scatter3_kernel(const int* gr, const int* gc, const float* gv,
                                const int* ur, const int* uc, const float* uv,
                                const int* pr, const int* pc, const float* pv,
                                int2* cs_geo, int2* cs_up, int2* cs_pu, int* cur_all) {
    int m = blockIdx.y;
    const int* rows; const int* cols; const float* vals; int2* cs; int* cur; int nnz;
    if (m == 0)      { rows=gr; cols=gc; vals=gv; cs=cs_geo; cur=cur_all;            nnz=NGNZ; }
    else if (m == 1) { rows=ur; cols=uc; vals=uv; cs=cs_up;  cur=cur_all+3*PP;       nnz=NUNZ; }
    else             { rows=pr; cols=pc; vals=pv; cs=cs_pu;  cur=cur_all+3*PP+UU;    nnz=NPUNZ; }
    int i0 = blockIdx.x * 2048 + threadIdx.x;
    #pragma unroll
    for (int k = 0; k < 8; k++) {
        int i = i0 + k * 256;
        if (i < nnz) {
            int p = atomicAdd(&cur[rows[i]], 1);
            cs[p] = make_int2(cols[i], __float_as_int(vals[i]));
        }
    }
}

// ---------------- gates: 16 rows/block, W reused 4x --------------------------------
__global__ void gates_kernel(const float* __restrict__ poi,
                             const float* __restrict__ wg, const float* __restrict__ bg,
                             const float* __restrict__ ws, const float* __restrict__ bs,
                             const float* __restrict__ wc, const float* __restrict__ bc,
                             float* __restrict__ og, float* __restrict__ os, float* __restrict__ oc) {
    __shared__ float spe[16][64];
    int t = threadIdx.x;
    int d = t & 63, r0 = t >> 6;
    int rowbase = blockIdx.x * 16;
    #pragma unroll
    for (int k = 0; k < 4; k++) {
        int li = t + k * 256;
        int rr = li >> 6, cc = li & 63;
        int grow = rowbase + rr;
        ((float*)spe)[li] = (grow < PP) ? poi[grow * 64 + cc] : 0.f;
    }
    __syncthreads();
    const float* W[3] = { wg, ws, wc };
    const float* Bv[3] = { bg, bs, bc };
    float* O[3] = { og, os, oc };
    #pragma unroll
    for (int g = 0; g < 3; g++) {
        const float* w = W[g];
        float bv = Bv[g][d];
        float a0 = bv, a1 = bv, a2 = bv, a3 = bv;
        #pragma unroll 8
        for (int j = 0; j < 64; j++) {
            float wv = __ldg(&w[j * 64 + d]);
            a0 = fmaf(spe[r0][j],      wv, a0);
            a1 = fmaf(spe[r0 + 4][j],  wv, a1);
            a2 = fmaf(spe[r0 + 8][j],  wv, a2);
            a3 = fmaf(spe[r0 + 12][j], wv, a3);
        }
        float accs[4] = { a0, a1, a2, a3 };
        #pragma unroll
        for (int k = 0; k < 4; k++) {
            int row = rowbase + r0 + k * 4;
            if (row < PP) {
                float sg = 1.f / (1.f + __expf(-accs[k]));
                O[g][row * 64 + d] = spe[r0 + k * 4][d] * sg;
            }
        }
    }
}

// ---------------- CSR SpMM: warp per row, nz split across half-warps ---------------
__global__ void spmm_kernel(const int* __restrict__ ptr, const int2* __restrict__ cs,
                            const float* __restrict__ x,
                            const float* __restrict__ add, float* __restrict__ out, int nrows) {
    int row = blockIdx.x * 8 + (threadIdx.x >> 5);
    if (row >= nrows) return;
    int lane = threadIdx.x & 31;
    int q = lane & 15, h = lane >> 4;
    int s = ptr[row], e = ptr[row + 1];
    const float4* x4 = (const float4*)x;
    float ax = 0.f, ay = 0.f, az = 0.f, aw = 0.f;
    int p = s + h;
    for (; p + 6 < e; p += 8) {
        int2 e0 = __ldg(&cs[p]),     e1 = __ldg(&cs[p + 2]);
        int2 e2 = __ldg(&cs[p + 4]), e3 = __ldg(&cs[p + 6]);
        float4 x0 = __ldg(&x4[e0.x * 16 + q]);
        float4 x1 = __ldg(&x4[e1.x * 16 + q]);
        float4 x2 = __ldg(&x4[e2.x * 16 + q]);
        float4 x3 = __ldg(&x4[e3.x * 16 + q]);
        float v0 = __int_as_float(e0.y), v1 = __int_as_float(e1.y);
        float v2 = __int_as_float(e2.y), v3 = __int_as_float(e3.y);
        ax = fmaf(v0, x0.x, ax); ay = fmaf(v0, x0.y, ay);
        az = fmaf(v0, x0.z, az); aw = fmaf(v0, x0.w, aw);
        ax = fmaf(v1, x1.x, ax); ay = fmaf(v1, x1.y, ay);
        az = fmaf(v1, x1.z, az); aw = fmaf(v1, x1.w, aw);
        ax = fmaf(v2, x2.x, ax); ay = fmaf(v2, x2.y, ay);
        az = fmaf(v2, x2.z, az); aw = fmaf(v2, x2.w, aw);
        ax = fmaf(v3, x3.x, ax); ay = fmaf(v3, x3.y, ay);
        az = fmaf(v3, x3.z, az); aw = fmaf(v3, x3.w, aw);
    }
    for (; p < e; p += 2) {
        int2 e0 = __ldg(&cs[p]);
        float4 x0 = __ldg(&x4[e0.x * 16 + q]);
        float v0 = __int_as_float(e0.y);
        ax = fmaf(v0, x0.x, ax); ay = fmaf(v0, x0.y, ay);
        az = fmaf(v0, x0.z, az); aw = fmaf(v0, x0.w, aw);
    }
    ax += __shfl_xor_sync(0xffffffffu, ax, 16);
    ay += __shfl_xor_sync(0xffffffffu, ay, 16);
    az += __shfl_xor_sync(0xffffffffu, az, 16);
    aw += __shfl_xor_sync(0xffffffffu, aw, 16);
    if (h == 0) {
        if (add) {
            float4 ad = ((const float4*)add)[row * 16 + q];
            ax += ad.x; ay += ad.y; az += ad.z; aw += ad.w;
        }
        ((float4*)out)[row * 16 + q] = make_float4(ax, ay, az, aw);
    }
}

// ---------------- fused final SpMM + avg3 + l2norm + bf16 --------------------------
__global__ void spmm_norm_kernel(const int* __restrict__ ptr, const int2* __restrict__ cs,
                                 const float* __restrict__ x, const float* __restrict__ w0,
                                 const float* __restrict__ prev,
                                 float* __restrict__ outf, __nv_bfloat16* __restrict__ hi) {
    int row = blockIdx.x * 8 + (threadIdx.x >> 5);
    if (row >= PPAD) return;
    int lane = threadIdx.x & 31;
    int q = lane & 15, h = lane >> 4;
    if (row >= PP) {
        if (h == 0) ((uint2*)hi)[row * 16 + q] = make_uint2(0u, 0u);
        return;
    }
    int s = ptr[row], e = ptr[row + 1];
    const float4* x4 = (const float4*)x;
    float ax = 0.f, ay = 0.f, az = 0.f, aw = 0.f;
    int p = s + h;
    for (; p + 6 < e; p += 8) {
        int2 e0 = __ldg(&cs[p]),     e1 = __ldg(&cs[p + 2]);
        int2 e2 = __ldg(&cs[p + 4]), e3 = __ldg(&cs[p + 6]);
        float4 x0 = __ldg(&x4[e0.x * 16 + q]);
        float4 x1 = __ldg(&x4[e1.x * 16 + q]);
        float4 x2 = __ldg(&x4[e2.x * 16 + q]);
        float4 x3 = __ldg(&x4[e3.x * 16 + q]);
        float v0 = __int_as_float(e0.y), v1 = __int_as_float(e1.y);
        float v2 = __int_as_float(e2.y), v3 = __int_as_float(e3.y);
        ax = fmaf(v0, x0.x, ax); ay = fmaf(v0, x0.y, ay);
        az = fmaf(v0, x0.z, az); aw = fmaf(v0, x0.w, aw);
        ax = fmaf(v1, x1.x, ax); ay = fmaf(v1, x1.y, ay);
        az = fmaf(v1, x1.z, az); aw = fmaf(v1, x1.w, aw);
        ax = fmaf(v2, x2.x, ax); ay = fmaf(v2, x2.y, ay);
        az = fmaf(v2, x2.z, az); aw = fmaf(v2, x2.w, aw);
        ax = fmaf(v3, x3.x, ax); ay = fmaf(v3, x3.y, ay);
        az = fmaf(v3, x3.z, az); aw = fmaf(v3, x3.w, aw);
    }
    for (; p < e; p += 2) {
        int2 e0 = __ldg(&cs[p]);
        float4 x0 = __ldg(&x4[e0.x * 16 + q]);
        float v0 = __int_as_float(e0.y);
        ax = fmaf(v0, x0.x, ax); ay = fmaf(v0, x0.y, ay);
        az = fmaf(v0, x0.z, az); aw = fmaf(v0, x0.w, aw);
    }
    ax += __shfl_xor_sync(0xffffffffu, ax, 16);
    ay += __shfl_xor_sync(0xffffffffu, ay, 16);
    az += __shfl_xor_sync(0xffffffffu, az, 16);
    aw += __shfl_xor_sync(0xffffffffu, aw, 16);

    float4 wr = __ldg(&((const float4*)w0)[row * 16 + q]);
    float4 pr = __ldg(&((const float4*)prev)[row * 16 + q]);
    const float third = 1.f / 3.f;
    float mx = (wr.x + 2.f * pr.x + ax) * third;
    float my = (wr.y + 2.f * pr.y + ay) * third;
    float mz = (wr.z + 2.f * pr.z + az) * third;
    float mw = (wr.w + 2.f * pr.w + aw) * third;
    float sq = mx * mx + my * my + mz * mz + mw * mw;
    #pragma unroll
    for (int o = 1; o < 16; o <<= 1) sq += __shfl_xor_sync(0xffffffffu, sq, o);
    float inv = 1.f / fmaxf(sqrtf(sq), 1e-12f);
    if (h == 0) {
        float nx = mx * inv, ny = my * inv, nz = mz * inv, nw = mw * inv;
        ((float4*)outf)[row * 16 + q] = make_float4(nx, ny, nz, nw);
        __nv_bfloat162 b0 = __floats2bfloat162_rn(nx, ny);
        __nv_bfloat162 b1 = __floats2bfloat162_rn(nz, nw);
        uint2 pk;
        pk.x = *(uint32_t*)&b0;
        pk.y = *(uint32_t*)&b1;
        ((uint2*)hi)[row * 16 + q] = pk;
    }
}

// fused 3-source SpMM (shared sparsity; aux-tail only)
__global__ void spmm3_kernel(const int* __restrict__ ptr, const int2* __restrict__ cs,
                             const float* __restrict__ x0, const float* __restrict__ x1,
                             const float* __restrict__ x2,
                             float* __restrict__ o0, float* __restrict__ o1,
                             float* __restrict__ o2, int nrows) {
    int row = blockIdx.x * 16 + (threadIdx.x >> 4);
    if (row >= nrows) return;
    int q = threadIdx.x & 15;
    int s = ptr[row], e = ptr[row + 1];
    const float4* X0 = (const float4*)x0;
    const float4* X1 = (const float4*)x1;
    const float4* X2 = (const float4*)x2;
    float4 a0 = make_float4(0, 0, 0, 0), a1 = a0, a2 = a0;
    for (int p = s; p < e; p++) {
        int2 ee = __ldg(&cs[p]);
        float v = __int_as_float(ee.y);
        int off = ee.x * 16 + q;
        float4 g0 = __ldg(&X0[off]);
        float4 g1 = __ldg(&X1[off]);
        float4 g2 = __ldg(&X2[off]);
        a0.x = fmaf(v, g0.x, a0.x); a0.y = fmaf(v, g0.y, a0.y);
        a0.z = fmaf(v, g0.z, a0.z); a0.w = fmaf(v, g0.w, a0.w);
        a1.x = fmaf(v, g1.x, a1.x); a1.y = fmaf(v, g1.y, a1.y);
        a1.z = fmaf(v, g1.z, a1.z); a1.w = fmaf(v, g1.w, a1.w);
        a2.x = fmaf(v, g2.x, a2.x); a2.y = fmaf(v, g2.y, a2.y);
        a2.z = fmaf(v, g2.z, a2.z); a2.w = fmaf(v, g2.w, a2.w);
    }
    ((float4*)o0)[row * 16 + q] = a0;
    ((float4*)o1)[row * 16 + q] = a1;
    ((float4*)o2)[row * 16 + q] = a2;
}

// ---------------- InfoNCE: block-row sweep, register double-buffer, 1 sync/tile ----
#define NCE_TSTRIDE 144
#define NCE_TBYTES  (128 * NCE_TSTRIDE)        // 18432
#define NCE_A    0
#define NCE_B0   NCE_TBYTES
#define NCE_B1   (2 * NCE_TBYTES)
#define NCE_SMEM (3 * NCE_TBYTES)              // 55296
#define NCE_CHUNK 20

__global__ void __launch_bounds__(256, 2) infonce_mma_kernel(
    const __nv_bfloat16* __restrict__ Ahi, const __nv_bfloat16* __restrict__ Bhi,
    float* __restrict__ rowsum, float* __restrict__ colsum) {
    extern __shared__ char smem[];
    uint32_t sb = smem_u32(smem);
    int tid = threadIdx.x;
    int wid = tid >> 5, lane = tid & 31;
    int by = blockIdx.y;
    int bx0 = blockIdx.x * NCE_CHUNK;
    int bx1 = min(79, bx0 + NCE_CHUNK);
    int warpM = wid >> 1, warpN = wid & 1;
    int lrow = lane & 15, lcol = (lane >> 4) << 4;
    int g = lane >> 2, q = lane & 3;
    bool rowfull = (by < 78);

    int crow[4], ccol[4];
    #pragma unroll
    for (int k = 0; k < 4; k++) {
        int i = tid + k * 256;
        crow[k] = i >> 3;
        ccol[k] = (i & 7) * 16;
    }

    // A tile (resident for whole sweep)
    {
        const uint4* s4 = (const uint4*)(Ahi + by * 128 * 64);
        char* d = smem + NCE_A;
        #pragma unroll
        for (int k = 0; k < 4; k++)
            *(uint4*)(d + crow[k] * NCE_TSTRIDE + ccol[k]) = __ldg(&s4[tid + k * 256]);
    }
    // first B tile: regs -> buf0
    uint4 breg[4];
    {
        const uint4* s4 = (const uint4*)(Bhi + bx0 * 128 * 64);
        #pragma unroll
        for (int k = 0; k < 4; k++) breg[k] = __ldg(&s4[tid + k * 256]);
        char* d = smem + NCE_B0;
        #pragma unroll
        for (int k = 0; k < 4; k++)
            *(uint4*)(d + crow[k] * NCE_TSTRIDE + ccol[k]) = breg[k];
    }
    __syncthreads();

    float rowtot[4] = { 0.f, 0.f, 0.f, 0.f };
    uint32_t aA = sb + NCE_A;
    int cur = 0;

    for (int bx = bx0; bx < bx1; bx++) {
        bool more = (bx + 1 < bx1);
        if (more) {
            const uint4* s4 = (const uint4*)(Bhi + (bx + 1) * 128 * 64);
            #pragma unroll
            for (int k = 0; k < 4; k++) breg[k] = __ldg(&s4[tid + k * 256]);
        }
        uint32_t aB = sb + (cur ? NCE_B1 : NCE_B0);

        float acc[2][8][4];
        #pragma unroll
        for (int mt = 0; mt < 2; mt++)
            #pragma unroll
            for (int nt = 0; nt < 8; nt++)
                #pragma unroll
                for (int d = 0; d < 4; d++) acc[mt][nt][d] = 0.f;

        #pragma unroll
        for (int kk = 0; kk < 4; kk++) {
            int koff = kk * 32 + lcol;
            uint32_t arow = (warpM * 32 + lrow) * NCE_TSTRIDE + koff;
            uint32_t brow = (warpN * 64 + lrow) * NCE_TSTRIDE + koff;
            uint32_t ah[2][4], bh[4][4];
            #pragma unroll
            for (int mt = 0; mt < 2; mt++)
                ldm4(ah[mt], aA + arow + mt * 16 * NCE_TSTRIDE);
            #pragma unroll
            for (int ng2 = 0; ng2 < 4; ng2++)
                ldm4(bh[ng2], aB + brow + ng2 * 16 * NCE_TSTRIDE);
            #pragma unroll
            for (int mt = 0; mt < 2; mt++)
                #pragma unroll
                for (int ng2 = 0; ng2 < 4; ng2++) {
                    mma16816(acc[mt][2 * ng2],     ah[mt], bh[ng2][0], bh[ng2][2]);
                    mma16816(acc[mt][2 * ng2 + 1], ah[mt], bh[ng2][1], bh[ng2][3]);
                }
        }

        float colacc[16];
        #pragma unroll
        for (int i = 0; i < 16; i++) colacc[i] = 0.f;

        if (rowfull && bx < 78) {
            #pragma unroll
            for (int mt = 0; mt < 2; mt++)
                #pragma unroll
                for (int nt = 0; nt < 8; nt++)
                    #pragma unroll
                    for (int d = 0; d < 4; d++) {
                        float e = fexp_logit(acc[mt][nt][d]);
                        rowtot[mt * 2 + (d >> 1)] += e;
                        colacc[nt * 2 + (d & 1)] += e;
                    }
            #pragma unroll
            for (int i = 0; i < 16; i++) {
                float v = colacc[i];
                v += __shfl_xor_sync(0xffffffffu, v, 4);
                v += __shfl_xor_sync(0xffffffffu, v, 8);
                v += __shfl_xor_sync(0xffffffffu, v, 16);
                if (g == 0)
                    atomicAdd(&colsum[bx * 128 + warpN * 64 + (i >> 1) * 8 + 2 * q + (i & 1)], v);
            }
        } else {
            #pragma unroll
            for (int mt = 0; mt < 2; mt++)
                #pragma unroll
                for (int nt = 0; nt < 8; nt++)
                    #pragma unroll
                    for (int d = 0; d < 4; d++) {
                        int rh = d >> 1, pr = d & 1;
                        int gr = by * 128 + warpM * 32 + mt * 16 + g + rh * 8;
                        int gc = bx * 128 + warpN * 64 + nt * 8 + 2 * q + pr;
                        float e = (gr < PP && gc < PP) ? fexp_logit(acc[mt][nt][d]) : 0.f;
                        rowtot[mt * 2 + rh] += e;
                        colacc[nt * 2 + pr] += e;
                    }
            #pragma unroll
            for (int i = 0; i < 16; i++) {
                float v = colacc[i];
                v += __shfl_xor_sync(0xffffffffu, v, 4);
                v += __shfl_xor_sync(0xffffffffu, v, 8);
                v += __shfl_xor_sync(0xffffffffu, v, 16);
                int gc = bx * 128 + warpN * 64 + (i >> 1) * 8 + 2 * q + (i & 1);
                if (g == 0 && gc < PP) atomicAdd(&colsum[gc], v);
            }
        }

        if (more) {
            char* d = smem + (cur ? NCE_B0 : NCE_B1);
            #pragma unroll
            for (int k = 0; k < 4; k++)
                *(uint4*)(d + crow[k] * NCE_TSTRIDE + ccol[k]) = breg[k];
        }
        __syncthreads();
        cur ^= 1;
    }

    #pragma unroll
    for (int r = 0; r < 4; r++) {
        float v = rowtot[r];
        v += __shfl_xor_sync(0xffffffffu, v, 1);
        v += __shfl_xor_sync(0xffffffffu, v, 2);
        int gr = by * 128 + warpM * 32 + (r >> 1) * 16 + g + (r & 1) * 8;
        if (q == 0 && gr < PP) atomicAdd(&rowsum[gr], v);
    }
}

// ---------------- loss reduction (grid-parallel, atomic) ---------------------------
__global__ void loss_kernel(const float* __restrict__ ng, const float* __restrict__ ns,
                            const float* __restrict__ rowsum, const float* __restrict__ colsum,
                            float* __restrict__ out) {
    __shared__ float sred[256];
    float t1 = 0.f;
    for (int i = blockIdx.x * 256 + threadIdx.x; i < PP; i += gridDim.x * 256) {
        const float4* a = (const float4*)&ng[i * 64];
        const float4* b = (const float4*)&ns[i * 64];
        float dot = 0.f;
        #pragma unroll
        for (int k = 0; k < 16; k++) {
            float4 x = __ldg(&a[k]), y = __ldg(&b[k]);
            dot += x.x * y.x + x.y * y.y + x.z * y.z + x.w * y.w;
        }
        float pos = fexp_logit(dot);
        t1 += -logf(pos / (rowsum[i] + 1e-8f) + 1e-8f);
        t1 += -logf(pos / (colsum[i] + 1e-8f) + 1e-8f);
    }
    sred[threadIdx.x] = t1;
    __syncthreads();
    for (int o = 128; o; o >>= 1) {
        if (threadIdx.x < o) sred[threadIdx.x] += sred[threadIdx.x + o];
        __syncthreads();
    }
    if (threadIdx.x == 0) atomicAdd(out, sred[0] * (0.5f / PP));
}

// ---------------- fused message MLP -> hg_users ------------------------------------
#define CST 452
__global__ void msg_kernel(const float* __restrict__ mg, const float* __restrict__ ms,
                           const float* __restrict__ mp, const float* __restrict__ ue,
                           const float* __restrict__ fw, const float* __restrict__ fb,
                           float* __restrict__ hu) {
    extern __shared__ float sm[];
    float4* fws = (float4*)sm;          // 448*16 float4
    float* cs = sm + 28672;             // 32 * CST floats
    int t = threadIdx.x;
    for (int i = t; i < 7168; i += 256) fws[i] = __ldg(&((const float4*)fw)[i]);
    int q = t & 15, ug = t >> 4;
    float4 fb4 = ((const float4*)fb)[q];
    int ubase = blockIdx.x * 32;
    #pragma unroll
    for (int s = 0; s < 2; s++) {
        int u = ubase + ug * 2 + s;
        float* cg = cs + (ug * 2 + s) * CST;
        float4 a = ((const float4*)mg)[u * 16 + q];
        float4 b = ((const float4*)ms)[u * 16 + q];
        float4 c = ((const float4*)mp)[u * 16 + q];
        float4 ab = make_float4(a.x*b.x, a.y*b.y, a.z*b.z, a.w*b.w);
        float4 ac = make_float4(a.x*c.x, a.y*c.y, a.z*c.z, a.w*c.w);
        float4 bc = make_float4(b.x*c.x, b.y*c.y, b.z*c.z, b.w*c.w);
        float4 abc = make_float4(ab.x*c.x, ab.y*c.y, ab.z*c.z, ab.w*c.w);
        *(float4*)&cg[0   + q*4] = a;
        *(float4*)&cg[64  + q*4] = b;
        *(float4*)&cg[128 + q*4] = c;
        *(float4*)&cg[192 + q*4] = ab;
        *(float4*)&cg[256 + q*4] = ac;
        *(float4*)&cg[320 + q*4] = bc;
        *(float4*)&cg[384 + q*4] = abc;
    }
    __syncthreads();
    float4 acc0 = make_float4(0,0,0,0), acc1 = make_float4(0,0,0,0);
    const float* cg0 = cs + (ug * 2) * CST;
    const float* cg1 = cg0 + CST;
    #pragma unroll 4
    for (int i = 0; i < 448; i++) {
        float4 w4 = fws[i * 16 + q];
        float s0 = cg0[i], s1 = cg1[i];
        acc0.x = fmaf(s0, w4.x, acc0.x); acc0.y = fmaf(s0, w4.y, acc0.y);
        acc0.z = fmaf(s0, w4.z, acc0.z); acc0.w = fmaf(s0, w4.w, acc0.w);
        acc1.x = fmaf(s1, w4.x, acc1.x); acc1.y = fmaf(s1, w4.y, acc1.y);
        acc1.z = fmaf(s1, w4.z, acc1.z); acc1.w = fmaf(s1, w4.w, acc1.w);
    }
    #pragma unroll
    for (int s = 0; s < 2; s++) {
        int u = ubase + ug * 2 + s;
        float4 acc = s ? acc1 : acc0;
        float4 me = make_float4(fb4.x + acc.x, fb4.y + acc.y, fb4.z + acc.z, fb4.w + acc.w);
        float4 u4 = ((const float4*)ue)[u * 16 + q];
        float4 r;
        r.x = me.x + u4.x + me.x * u4.x;
        r.y = me.y + u4.y + me.y * u4.y;
        r.z = me.z + u4.z + me.z * u4.z;
        r.w = me.w + u4.w + me.w * u4.w;
        ((float4*)hu)[u * 16 + q] = r;
    }
}

// ---------------- fusion_pois / batch_users ---------------------------------------
__global__ void fusion_kernel(const float* __restrict__ colg, const float* __restrict__ s,
                              const float* __restrict__ ng, const float* __restrict__ ns,
                              float* __restrict__ out) {
    int row = blockIdx.x * 8 + (threadIdx.x >> 5);
    if (row >= PP) return;
    int lane = threadIdx.x & 31;
    int i = row * 32 + lane;
    float2 vc = ((const float2*)colg)[i], vs = ((const float2*)s)[i];
    float vx = vc.x + vs.x, vy = vc.y + vs.y;
    float sq = vx * vx + vy * vy;
    #pragma unroll
    for (int o = 16; o; o >>= 1) sq += __shfl_xor_sync(0xffffffffu, sq, o);
    float inv = 1.f / fmaxf(sqrtf(sq), 1e-12f);
    float2 vg = ((const float2*)ng)[i], vn = ((const float2*)ns)[i];
    ((float2*)out)[i] = make_float2(vx * inv + vg.x + vn.x, vy * inv + vg.y + vn.y);
}

__global__ void batch_kernel(const float* __restrict__ us, const int* __restrict__ uidx,
                             float* __restrict__ out) {
    int b = blockIdx.x * 8 + (threadIdx.x >> 5);
    if (b >= BBATCH) return;
    int lane = threadIdx.x & 31;
    int u = __ldg(&uidx[b]);
    float2 v = ((const float2*)us)[u * 32 + lane];
    float sq = v.x * v.x + v.y * v.y;
    #pragma unroll
    for (int o = 16; o; o >>= 1) sq += __shfl_xor_sync(0xffffffffu, sq, o);
    float inv = 1.f / fmaxf(sqrtf(sq), 1e-12f);
    ((float2*)out)[b * 32 + lane] = make_float2(v.x * inv, v.y * inv);
}

// ---------------- host side --------------------------------------------------------
static void* getsym(const void* shadow) {
    void* p = nullptr;
    cudaGetSymbolAddress(&p, shadow);
    return p;
}

extern "C" void kernel_launch(void* const* d_in, const int* in_sizes, int n_in,
                              void* d_out, int out_size) {
    const float* poi_emb  = (const float*)d_in[0];
    const float* user_emb = (const float*)d_in[1];
    const float* w_geo    = (const float*)d_in[2];
    const float* b_geo    = (const float*)d_in[3];
    const float* w_seq    = (const float*)d_in[4];
    const float* b_seq    = (const float*)d_in[5];
    const float* w_col    = (const float*)d_in[6];
    const float* b_col    = (const float*)d_in[7];
    const float* fusion_w = (const float*)d_in[8];
    const float* fusion_b = (const float*)d_in[9];
    const float* geo_vals = (const float*)d_in[10];
    const float* src_vals = (const float*)d_in[11];
    const float* tar_vals = (const float*)d_in[12];
    const float* up_vals  = (const float*)d_in[13];
    const float* pu_vals  = (const float*)d_in[14];
    const int* geo_rows = (const int*)d_in[15];
    const int* geo_cols = (const int*)d_in[16];
    const int* src_rows = (const int*)d_in[17];
    const int* src_cols = (const int*)d_in[18];
    const int* tar_rows = (const int*)d_in[19];
    const int* tar_cols = (const int*)d_in[20];
    const int* up_rows  = (const int*)d_in[21];
    const int* up_cols  = (const int*)d_in[22];
    const int* pu_rows  = (const int*)d_in[23];
    const int* pu_cols  = (const int*)d_in[24];
    const int* user_idx = (const int*)d_in[25];
    float* out = (float*)d_out;

    float* Ggeo = (float*)getsym(g_Ggeo);
    float* Gseq = (float*)getsym(g_Gseq);
    float* Colg = (float*)getsym(g_Colg);
    float* T1 = (float*)getsym(g_T1);
    float* T3 = (float*)getsym(g_T3);
    float* T4 = (float*)getsym(g_T4);
    float* NGv = (float*)getsym(g_NGb);
    float* NSv = (float*)getsym(g_NSb);
    __nv_bfloat16* NGhi = (__nv_bfloat16*)getsym(g_NGhi);
    __nv_bfloat16* NShi = (__nv_bfloat16*)getsym(g_NShi);
    float* MG = (float*)getsym(g_MG);
    float* MS = (float*)getsym(g_MS);
    float* MP = (float*)getsym(g_MP);
    float* HU = (float*)getsym(g_HU);
    float* US = (float*)getsym(g_US);
    float* rowsum = (float*)getsym(g_rowsum);
    float* colsum = (float*)getsym(g_colsum);
    int* cnt_all = (int*)getsym(g_cnt_all);
    int* cur_all = (int*)getsym(g_cur_all);
    int* ptr_geo = (int*)getsym(g_ptr_geo);
    int* ptr_src = (int*)getsym(g_ptr_src);
    int* ptr_tar = (int*)getsym(g_ptr_tar);
    int* ptr_pu  = (int*)getsym(g_ptr_pu);
    int* ptr_up  = (int*)getsym(g_ptr_up);
    int2* cs_geo = (int2*)getsym(g_cs_geo);
    int2* cs_src = (int2*)getsym(g_cs_src);
    int2* cs_tar = (int2*)getsym(g_cs_tar);
    int2* cs_up  = (int2*)getsym(g_cs_up);
    int2* cs_pu  = (int2*)getsym(g_cs_pu);

    cudaFuncSetAttribute(infonce_mma_kernel, cudaFuncAttributeMaxDynamicSharedMemorySize,
                         NCE_SMEM);
    cudaFuncSetAttribute(msg_kernel, cudaFuncAttributeMaxDynamicSharedMemorySize, 180000);

    // static stream + events: created ONCE on the first (correctness) call.
    static cudaStream_t aux = nullptr;
    static cudaEvent_t evFork, evGates, evGeo, evNS, evTail;
    if (aux == nullptr) {
        cudaStreamCreateWithFlags(&aux, cudaStreamNonBlocking);
        cudaEventCreateWithFlags(&evFork, cudaEventDisableTiming);
        cudaEventCreateWithFlags(&evGates, cudaEventDisableTiming);
        cudaEventCreateWithFlags(&evGeo, cudaEventDisableTiming);
        cudaEventCreateWithFlags(&evNS, cudaEventDisableTiming);
        cudaEventCreateWithFlags(&evTail, cudaEventDisableTiming);
    }

    const int gridPW = (PP + 7) / 8, gridUW = (UU + 7) / 8;
    const int gridPdW = (PPAD + 7) / 8;
    const int gridU16 = (UU + 15) / 16;
    const int gridP8 = (PP + 7) / 8;

    // ---- fork: gates + aux-zero on aux || zero(tar,src) + CSR(tar,src) on main ----
    cudaEventRecord(evFork, 0);
    cudaStreamWaitEvent(aux, evFork, 0);
    gates_kernel<<<(PP + 15) / 16, 256, 0, aux>>>(poi_emb, w_geo, b_geo, w_seq, b_seq,
                                                  w_col, b_col, Ggeo, Gseq, Colg);
    cudaEventRecord(evGates, aux);
    zero_aux_kernel<<<(PP + UU + 255) / 256, 256, 0, aux>>>(cnt_all, rowsum, colsum,
                                                            out + OUT_LOSS);

    zero_main_kernel<<<(2 * PP + 255) / 256, 256>>>(cnt_all);
    dim3 gh2((NDNZ + 2047) / 2048, 2);
    hist2_kernel<<<gh2, 256>>>(tar_rows, src_rows, cnt_all);
    scan2_kernel<<<2, 1024>>>(cnt_all, cur_all, ptr_tar, ptr_src);
    scatter2_kernel<<<gh2, 256>>>(tar_rows, tar_cols, tar_vals,
                                  src_rows, src_cols, src_vals,
                                  cs_tar, cs_src, cur_all);
    cudaStreamWaitEvent(0, evGates, 0);
    spmm_kernel<<<gridPW, 256>>>(ptr_tar, cs_tar, Gseq, nullptr, T3, PP);
    spmm_kernel<<<gridPW, 256>>>(ptr_src, cs_src, T3, Gseq, T4, PP);
    spmm_kernel<<<gridPW, 256>>>(ptr_tar, cs_tar, T4, nullptr, T3, PP);
    spmm_norm_kernel<<<gridPdW, 256>>>(ptr_src, cs_src, T3, Gseq, T4, NSv, NShi);
    cudaEventRecord(evNS, 0);

    // aux: CSR(geo,up,pu) + geo chain
    dim3 gh3((NPUNZ + 2047) / 2048, 3);
    hist3_kernel<<<gh3, 256, 0, aux>>>(geo_rows, up_rows, pu_rows, cnt_all);
    scan3_kernel<<<3, 1024, 0, aux>>>(cnt_all, cur_all, ptr_geo, ptr_up, ptr_pu);
    scatter3_kernel<<<gh3, 256, 0, aux>>>(geo_rows, geo_cols, geo_vals,
                                          up_rows, up_cols, up_vals,
                                          pu_rows, pu_cols, pu_vals,
                                          cs_geo, cs_up, cs_pu, cur_all);
    spmm_kernel<<<gridPW, 256, 0, aux>>>(ptr_geo, cs_geo, Ggeo, Ggeo, T1, PP);
    spmm_norm_kernel<<<gridPdW, 256, 0, aux>>>(ptr_geo, cs_geo, T1, Ggeo, T1, NGv, NGhi);
    cudaEventRecord(evGeo, aux);

    // main: infonce + loss (needs NG from aux)
    cudaStreamWaitEvent(0, evGeo, 0);
    dim3 gnce(4, PPAD / 128);
    infonce_mma_kernel<<<gnce, 256, NCE_SMEM>>>(NGhi, NShi, rowsum, colsum);
    loss_kernel<<<40, 256>>>(NGv, NSv, rowsum, colsum, out + OUT_LOSS);

    // aux: multi-view tail (needs NS from main; geo/up/pu CSR and NG/Colg local)
    cudaStreamWaitEvent(aux, evNS, 0);
    spmm3_kernel<<<gridU16, 256, 0, aux>>>(ptr_up, cs_up, NGv, NSv, Colg, MG, MS, MP, UU);
    msg_kernel<<<250, 256, (28672 + 32 * CST) * sizeof(float), aux>>>(MG, MS, MP, user_emb,
                                                                      fusion_w, fusion_b, HU);
    spmm_kernel<<<gridPW, 256, 0, aux>>>(ptr_pu, cs_pu, HU, nullptr, T1, PP);
    fusion_kernel<<<gridP8, 256, 0, aux>>>(Colg, T1, NGv, NSv, out + OUT_FUS);
    spmm_kernel<<<gridUW, 256, 0, aux>>>(ptr_up, cs_up, out + OUT_FUS, nullptr, US, UU);
    batch_kernel<<<(BBATCH + 7) / 8, 256, 0, aux>>>(US, user_idx, out + OUT_BATCH);
    cudaEventRecord(evTail, aux);
    cudaStreamWaitEvent(0, evTail, 0);
}

// round 17
// speedup vs baseline: 1.0510x; 1.0510x over previous
#include <cuda_runtime.h>
#include <cuda_bf16.h>
#include <math.h>
#include <stdint.h>

#define PP   10000
#define UU   8000
#define DD   64
#define BBATCH 4096
#define NGNZ 320000
#define NDNZ 320000
#define NUNZ 400000
#define NPUNZ 400000
#define PPAD 10112            // 79 * 128

#define OUT_BATCH 0
#define OUT_FUS   (BBATCH*DD)
#define OUT_LOSS  (OUT_FUS + PP*DD)

#define CNT_ALL_N (4*PP + UU)

// ---------------- scratch (static device memory) ---------------------------------
__device__ float g_Ggeo[PP*DD], g_Gseq[PP*DD], g_Colg[PP*DD];
__device__ float g_T1[PP*DD], g_T3[PP*DD], g_T4[PP*DD];
__device__ float g_NGb[PP*DD], g_NSb[PP*DD];
__device__ __nv_bfloat16 g_NGhi[PPAD*DD], g_NShi[PPAD*DD];
__device__ float g_MG[UU*DD], g_MS[UU*DD], g_MP[UU*DD], g_HU[UU*DD], g_US[UU*DD];
__device__ float g_rowsum[PP], g_colsum[PP];
__device__ int   g_cnt_all[CNT_ALL_N], g_cur_all[CNT_ALL_N];
__device__ int   g_ptr_geo[PP+1], g_ptr_src[PP+1], g_ptr_tar[PP+1], g_ptr_pu[PP+1], g_ptr_up[UU+1];
__device__ int2  g_cs_geo[NGNZ], g_cs_src[NDNZ], g_cs_tar[NDNZ], g_cs_up[NUNZ], g_cs_pu[NPUNZ];

// ---------------- fast exp via MUFU.EX2 (SFU pipe, frees FMA pipe) -----------------
__device__ __forceinline__ float fexp_logit(float x) {    // exp(x/T) = exp(5x)
    float y = x * 7.2134752044448169f;                    // 5 * log2(e)
    float r;
    asm("ex2.approx.f32 %0, %1;" : "=f"(r) : "f"(y));
    return r;
}

// ---------------- warp-MMA helpers (portable PTX: no tcgen05) ----------------------
__device__ __forceinline__ uint32_t smem_u32(const void* p) {
    uint32_t a;
    asm("{ .reg .u64 t; cvta.to.shared.u64 t, %1; cvt.u32.u64 %0, t; }" : "=r"(a) : "l"(p));
    return a;
}
__device__ __forceinline__ void ldm4(uint32_t* r, uint32_t addr) {
    asm volatile("ldmatrix.sync.aligned.m8n8.x4.shared.b16 {%0,%1,%2,%3}, [%4];"
                 : "=r"(r[0]), "=r"(r[1]), "=r"(r[2]), "=r"(r[3]) : "r"(addr));
}
__device__ __forceinline__ void mma16816(float* d, const uint32_t* a, uint32_t b0, uint32_t b1) {
    asm volatile("mma.sync.aligned.m16n8k16.row.col.f32.bf16.bf16.f32 "
                 "{%0,%1,%2,%3}, {%4,%5,%6,%7}, {%8,%9}, {%0,%1,%2,%3};"
                 : "+f"(d[0]), "+f"(d[1]), "+f"(d[2]), "+f"(d[3])
                 : "r"(a[0]), "r"(a[1]), "r"(a[2]), "r"(a[3]), "r"(b0), "r"(b1));
}

// ---------------- CSR build --------------------------------------------------------
__global__ void zero_main_kernel(int* cnt_all) {
    int i = blockIdx.x * 256 + threadIdx.x;
    if (i < 2 * PP) cnt_all[PP + i] = 0;     // src @ [PP,2PP), tar @ [2PP,3PP)
}
__global__ void zero_aux_kernel(int* cnt_all, float* rowsum, float* colsum, float* lossp) {
    int i = blockIdx.x * 256 + threadIdx.x;
    if (i < PP) cnt_all[i] = 0;                              // geo
    if (i < PP + UU) cnt_all[3 * PP + i] = 0;                // up + pu
    if (i < PP) { rowsum[i] = 0.f; colsum[i] = 0.f; }
    if (i == 0) lossp[0] = 0.f;
}

// ILP-2 histograms (L2-atomic-throughput bound: maximize concurrent blocks)
__global__ void hist2_kernel(const int* tar, const int* src, int* cnt_all) {
    int m = blockIdx.y;
    const int* rows = m ? src : tar;
    int base = m ? PP : 2 * PP;
    int i0 = blockIdx.x * 512 + threadIdx.x;
    #pragma unroll
    for (int k = 0; k < 2; k++) {
        int i = i0 + k * 256;
        if (i < NDNZ) atomicAdd(&cnt_all[base + rows[i]], 1);
    }
}
__global__ void hist3_kernel(const int* geo, const int* up, const int* pu, int* cnt_all) {
    int m = blockIdx.y;
    const int* rows; int base, nnz;
    if (m == 0)      { rows = geo; base = 0;          nnz = NGNZ; }
    else if (m == 1) { rows = up;  base = 3*PP;       nnz = NUNZ; }
    else             { rows = pu;  base = 3*PP + UU;  nnz = NPUNZ; }
    int i0 = blockIdx.x * 512 + threadIdx.x;
    #pragma unroll
    for (int k = 0; k < 2; k++) {
        int i = i0 + k * 256;
        if (i < nnz) atomicAdd(&cnt_all[base + rows[i]], 1);
    }
}

// single-block scan over one segment, 8 elements/thread (8192 per sweep)
__device__ __forceinline__ void scan_seg(const int* __restrict__ cnt, int* __restrict__ ptr,
                                         int* __restrict__ cur, int n) {
    __shared__ int wsum[32];
    __shared__ int carry;
    int t = threadIdx.x, lane = t & 31, w = t >> 5;
    if (t == 0) { carry = 0; ptr[0] = 0; }
    __syncthreads();
    for (int c0 = 0; c0 < n; c0 += 8192) {
        int idx = c0 + 8 * t;
        int v[8];
        #pragma unroll
        for (int j = 0; j < 8; j++)
            v[j] = (idx + j < n) ? cnt[idx + j] : 0;
        int s = 0;
        #pragma unroll
        for (int j = 0; j < 8; j++) s += v[j];
        #pragma unroll
        for (int off = 1; off < 32; off <<= 1) {
            int y = __shfl_up_sync(0xffffffffu, s, off);
            if (lane >= off) s += y;
        }
        if (lane == 31) wsum[w] = s;
        __syncthreads();
        if (w == 0) {
            int ws = wsum[lane];
            #pragma unroll
            for (int off = 1; off < 32; off <<= 1) {
                int y = __shfl_up_sync(0xffffffffu, ws, off);
                if (lane >= off) ws += y;
            }
            wsum[lane] = ws;
        }
        __syncthreads();
        int add = carry + (w ? wsum[w - 1] : 0);
        int incl[8];
        incl[7] = s + add;
        #pragma unroll
        for (int j = 6; j >= 0; j--) incl[j] = incl[j + 1] - v[j + 1];
        #pragma unroll
        for (int j = 0; j < 8; j++) {
            if (idx + j < n) {
                ptr[idx + j + 1] = incl[j];
                cur[idx + j] = incl[j] - v[j];
            }
        }
        __syncthreads();
        if (t == 0) carry += wsum[31];
        __syncthreads();
    }
}
__global__ void scan2_kernel(const int* cnt_all, int* cur_all, int* ptr_tar, int* ptr_src) {
    if (blockIdx.x == 0) scan_seg(cnt_all + 2*PP, ptr_tar, cur_all + 2*PP, PP);
    else                 scan_seg(cnt_all + PP,   ptr_src, cur_all + PP,   PP);
}
__global__ void scan3_kernel(const int* cnt_all, int* cur_all,
                             int* ptr_geo, int* ptr_up, int* ptr_pu) {
    if (blockIdx.x == 0)      scan_seg(cnt_all,              ptr_geo, cur_all,              PP);
    else if (blockIdx.x == 1) scan_seg(cnt_all + 3*PP,       ptr_up,  cur_all + 3*PP,       UU);
    else                      scan_seg(cnt_all + 3*PP + UU,  ptr_pu,  cur_all + 3*PP + UU,  PP);
}

// ILP-4 scatters (round-15 config)
__global__ void scatter2_kernel(const int* tr, const int* tc, const float* tv,
                                const int* sr, const int* sc, const float* sv,
                                int2* cs_tar, int2* cs_src, int* cur_all) {
    int m = blockIdx.y;
    const int* rows = m ? sr : tr;
    const int* cols = m ? sc : tc;
    const float* vals = m ? sv : tv;
    int2* cs = m ? cs_src : cs_tar;
    int* cur = cur_all + (m ? PP : 2 * PP);
    int i0 = blockIdx.x * 1024 + threadIdx.x;
    #pragma unroll
    for (int k = 0; k < 4; k++) {
        int i = i0 + k * 256;
        if (i < NDNZ) {
            int p = atomicAdd(&cur[rows[i]], 1);
            cs[p] = make_int2(cols[i], __float_as_int(vals[i]));
        }
    }
}
__global__ void scatter3_kernel(const int* gr, const int* gc, const float* gv,
                                const int* ur, const int* uc, const float* uv,
                                const int* pr, const int* pc, const float* pv,
                                int2* cs_geo, int2* cs_up, int2* cs_pu, int* cur_all) {
    int m = blockIdx.y;
    const int* rows; const int* cols; const float* vals; int2* cs; int* cur; int nnz;
    if (m == 0)      { rows=gr; cols=gc; vals=gv; cs=cs_geo; cur=cur_all;            nnz=NGNZ; }
    else if (m == 1) { rows=ur; cols=uc; vals=uv; cs=cs_up;  cur=cur_all+3*PP;       nnz=NUNZ; }
    else             { rows=pr; cols=pc; vals=pv; cs=cs_pu;  cur=cur_all+3*PP+UU;    nnz=NPUNZ; }
    int i0 = blockIdx.x * 1024 + threadIdx.x;
    #pragma unroll
    for (int k = 0; k < 4; k++) {
        int i = i0 + k * 256;
        if (i < nnz) {
            int p = atomicAdd(&cur[rows[i]], 1);
            cs[p] = make_int2(cols[i], __float_as_int(vals[i]));
        }
    }
}

// ---------------- gates: 16 rows/block, W reused 4x --------------------------------
__global__ void gates_kernel(const float* __restrict__ poi,
                             const float* __restrict__ wg, const float* __restrict__ bg,
                             const float* __restrict__ ws, const float* __restrict__ bs,
                             const float* __restrict__ wc, const float* __restrict__ bc,
                             float* __restrict__ og, float* __restrict__ os, float* __restrict__ oc) {
    __shared__ float spe[16][64];
    int t = threadIdx.x;
    int d = t & 63, r0 = t >> 6;
    int rowbase = blockIdx.x * 16;
    #pragma unroll
    for (int k = 0; k < 4; k++) {
        int li = t + k * 256;
        int rr = li >> 6, cc = li & 63;
        int grow = rowbase + rr;
        ((float*)spe)[li] = (grow < PP) ? poi[grow * 64 + cc] : 0.f;
    }
    __syncthreads();
    const float* W[3] = { wg, ws, wc };
    const float* Bv[3] = { bg, bs, bc };
    float* O[3] = { og, os, oc };
    #pragma unroll
    for (int g = 0; g < 3; g++) {
        const float* w = W[g];
        float bv = Bv[g][d];
        float a0 = bv, a1 = bv, a2 = bv, a3 = bv;
        #pragma unroll 8
        for (int j = 0; j < 64; j++) {
            float wv = __ldg(&w[j * 64 + d]);
            a0 = fmaf(spe[r0][j],      wv, a0);
            a1 = fmaf(spe[r0 + 4][j],  wv, a1);
            a2 = fmaf(spe[r0 + 8][j],  wv, a2);
            a3 = fmaf(spe[r0 + 12][j], wv, a3);
        }
        float accs[4] = { a0, a1, a2, a3 };
        #pragma unroll
        for (int k = 0; k < 4; k++) {
            int row = rowbase + r0 + k * 4;
            if (row < PP) {
                float sg = 1.f / (1.f + __expf(-accs[k]));
                O[g][row * 64 + d] = spe[r0 + k * 4][d] * sg;
            }
        }
    }
}

// ---------------- CSR SpMM: warp per row, nz split across half-warps ---------------
__global__ void spmm_kernel(const int* __restrict__ ptr, const int2* __restrict__ cs,
                            const float* __restrict__ x,
                            const float* __restrict__ add, float* __restrict__ out, int nrows) {
    int row = blockIdx.x * 8 + (threadIdx.x >> 5);
    if (row >= nrows) return;
    int lane = threadIdx.x & 31;
    int q = lane & 15, h = lane >> 4;
    int s = ptr[row], e = ptr[row + 1];
    const float4* x4 = (const float4*)x;
    float ax = 0.f, ay = 0.f, az = 0.f, aw = 0.f;
    int p = s + h;
    for (; p + 6 < e; p += 8) {
        int2 e0 = __ldg(&cs[p]),     e1 = __ldg(&cs[p + 2]);
        int2 e2 = __ldg(&cs[p + 4]), e3 = __ldg(&cs[p + 6]);
        float4 x0 = __ldg(&x4[e0.x * 16 + q]);
        float4 x1 = __ldg(&x4[e1.x * 16 + q]);
        float4 x2 = __ldg(&x4[e2.x * 16 + q]);
        float4 x3 = __ldg(&x4[e3.x * 16 + q]);
        float v0 = __int_as_float(e0.y), v1 = __int_as_float(e1.y);
        float v2 = __int_as_float(e2.y), v3 = __int_as_float(e3.y);
        ax = fmaf(v0, x0.x, ax); ay = fmaf(v0, x0.y, ay);
        az = fmaf(v0, x0.z, az); aw = fmaf(v0, x0.w, aw);
        ax = fmaf(v1, x1.x, ax); ay = fmaf(v1, x1.y, ay);
        az = fmaf(v1, x1.z, az); aw = fmaf(v1, x1.w, aw);
        ax = fmaf(v2, x2.x, ax); ay = fmaf(v2, x2.y, ay);
        az = fmaf(v2, x2.z, az); aw = fmaf(v2, x2.w, aw);
        ax = fmaf(v3, x3.x, ax); ay = fmaf(v3, x3.y, ay);
        az = fmaf(v3, x3.z, az); aw = fmaf(v3, x3.w, aw);
    }
    for (; p < e; p += 2) {
        int2 e0 = __ldg(&cs[p]);
        float4 x0 = __ldg(&x4[e0.x * 16 + q]);
        float v0 = __int_as_float(e0.y);
        ax = fmaf(v0, x0.x, ax); ay = fmaf(v0, x0.y, ay);
        az = fmaf(v0, x0.z, az); aw = fmaf(v0, x0.w, aw);
    }
    ax += __shfl_xor_sync(0xffffffffu, ax, 16);
    ay += __shfl_xor_sync(0xffffffffu, ay, 16);
    az += __shfl_xor_sync(0xffffffffu, az, 16);
    aw += __shfl_xor_sync(0xffffffffu, aw, 16);
    if (h == 0) {
        if (add) {
            float4 ad = ((const float4*)add)[row * 16 + q];
            ax += ad.x; ay += ad.y; az += ad.z; aw += ad.w;
        }
        ((float4*)out)[row * 16 + q] = make_float4(ax, ay, az, aw);
    }
}

// ---------------- fused final SpMM + avg3 + l2norm + bf16 --------------------------
__global__ void spmm_norm_kernel(const int* __restrict__ ptr, const int2* __restrict__ cs,
                                 const float* __restrict__ x, const float* __restrict__ w0,
                                 const float* __restrict__ prev,
                                 float* __restrict__ outf, __nv_bfloat16* __restrict__ hi) {
    int row = blockIdx.x * 8 + (threadIdx.x >> 5);
    if (row >= PPAD) return;
    int lane = threadIdx.x & 31;
    int q = lane & 15, h = lane >> 4;
    if (row >= PP) {
        if (h == 0) ((uint2*)hi)[row * 16 + q] = make_uint2(0u, 0u);
        return;
    }
    int s = ptr[row], e = ptr[row + 1];
    const float4* x4 = (const float4*)x;
    float ax = 0.f, ay = 0.f, az = 0.f, aw = 0.f;
    int p = s + h;
    for (; p + 6 < e; p += 8) {
        int2 e0 = __ldg(&cs[p]),     e1 = __ldg(&cs[p + 2]);
        int2 e2 = __ldg(&cs[p + 4]), e3 = __ldg(&cs[p + 6]);
        float4 x0 = __ldg(&x4[e0.x * 16 + q]);
        float4 x1 = __ldg(&x4[e1.x * 16 + q]);
        float4 x2 = __ldg(&x4[e2.x * 16 + q]);
        float4 x3 = __ldg(&x4[e3.x * 16 + q]);
        float v0 = __int_as_float(e0.y), v1 = __int_as_float(e1.y);
        float v2 = __int_as_float(e2.y), v3 = __int_as_float(e3.y);
        ax = fmaf(v0, x0.x, ax); ay = fmaf(v0, x0.y, ay);
        az = fmaf(v0, x0.z, az); aw = fmaf(v0, x0.w, aw);
        ax = fmaf(v1, x1.x, ax); ay = fmaf(v1, x1.y, ay);
        az = fmaf(v1, x1.z, az); aw = fmaf(v1, x1.w, aw);
        ax = fmaf(v2, x2.x, ax); ay = fmaf(v2, x2.y, ay);
        az = fmaf(v2, x2.z, az); aw = fmaf(v2, x2.w, aw);
        ax = fmaf(v3, x3.x, ax); ay = fmaf(v3, x3.y, ay);
        az = fmaf(v3, x3.z, az); aw = fmaf(v3, x3.w, aw);
    }
    for (; p < e; p += 2) {
        int2 e0 = __ldg(&cs[p]);
        float4 x0 = __ldg(&x4[e0.x * 16 + q]);
        float v0 = __int_as_float(e0.y);
        ax = fmaf(v0, x0.x, ax); ay = fmaf(v0, x0.y, ay);
        az = fmaf(v0, x0.z, az); aw = fmaf(v0, x0.w, aw);
    }
    ax += __shfl_xor_sync(0xffffffffu, ax, 16);
    ay += __shfl_xor_sync(0xffffffffu, ay, 16);
    az += __shfl_xor_sync(0xffffffffu, az, 16);
    aw += __shfl_xor_sync(0xffffffffu, aw, 16);

    float4 wr = __ldg(&((const float4*)w0)[row * 16 + q]);
    float4 pr = __ldg(&((const float4*)prev)[row * 16 + q]);
    const float third = 1.f / 3.f;
    float mx = (wr.x + 2.f * pr.x + ax) * third;
    float my = (wr.y + 2.f * pr.y + ay) * third;
    float mz = (wr.z + 2.f * pr.z + az) * third;
    float mw = (wr.w + 2.f * pr.w + aw) * third;
    float sq = mx * mx + my * my + mz * mz + mw * mw;
    #pragma unroll
    for (int o = 1; o < 16; o <<= 1) sq += __shfl_xor_sync(0xffffffffu, sq, o);
    float inv = 1.f / fmaxf(sqrtf(sq), 1e-12f);
    if (h == 0) {
        float nx = mx * inv, ny = my * inv, nz = mz * inv, nw = mw * inv;
        ((float4*)outf)[row * 16 + q] = make_float4(nx, ny, nz, nw);
        __nv_bfloat162 b0 = __floats2bfloat162_rn(nx, ny);
        __nv_bfloat162 b1 = __floats2bfloat162_rn(nz, nw);
        uint2 pk;
        pk.x = *(uint32_t*)&b0;
        pk.y = *(uint32_t*)&b1;
        ((uint2*)hi)[row * 16 + q] = pk;
    }
}

// fused 3-source SpMM (shared sparsity; aux-tail only)
__global__ void spmm3_kernel(const int* __restrict__ ptr, const int2* __restrict__ cs,
                             const float* __restrict__ x0, const float* __restrict__ x1,
                             const float* __restrict__ x2,
                             float* __restrict__ o0, float* __restrict__ o1,
                             float* __restrict__ o2, int nrows) {
    int row = blockIdx.x * 16 + (threadIdx.x >> 4);
    if (row >= nrows) return;
    int q = threadIdx.x & 15;
    int s = ptr[row], e = ptr[row + 1];
    const float4* X0 = (const float4*)x0;
    const float4* X1 = (const float4*)x1;
    const float4* X2 = (const float4*)x2;
    float4 a0 = make_float4(0, 0, 0, 0), a1 = a0, a2 = a0;
    for (int p = s; p < e; p++) {
        int2 ee = __ldg(&cs[p]);
        float v = __int_as_float(ee.y);
        int off = ee.x * 16 + q;
        float4 g0 = __ldg(&X0[off]);
        float4 g1 = __ldg(&X1[off]);
        float4 g2 = __ldg(&X2[off]);
        a0.x = fmaf(v, g0.x, a0.x); a0.y = fmaf(v, g0.y, a0.y);
        a0.z = fmaf(v, g0.z, a0.z); a0.w = fmaf(v, g0.w, a0.w);
        a1.x = fmaf(v, g1.x, a1.x); a1.y = fmaf(v, g1.y, a1.y);
        a1.z = fmaf(v, g1.z, a1.z); a1.w = fmaf(v, g1.w, a1.w);
        a2.x = fmaf(v, g2.x, a2.x); a2.y = fmaf(v, g2.y, a2.y);
        a2.z = fmaf(v, g2.z, a2.z); a2.w = fmaf(v, g2.w, a2.w);
    }
    ((float4*)o0)[row * 16 + q] = a0;
    ((float4*)o1)[row * 16 + q] = a1;
    ((float4*)o2)[row * 16 + q] = a2;
}

// ---------------- InfoNCE: block-row sweep, register double-buffer, 1 sync/tile ----
#define NCE_TSTRIDE 144
#define NCE_TBYTES  (128 * NCE_TSTRIDE)        // 18432
#define NCE_A    0
#define NCE_B0   NCE_TBYTES
#define NCE_B1   (2 * NCE_TBYTES)
#define NCE_SMEM (3 * NCE_TBYTES)              // 55296
#define NCE_CHUNK 10

__global__ void __launch_bounds__(256, 2) infonce_mma_kernel(
    const __nv_bfloat16* __restrict__ Ahi, const __nv_bfloat16* __restrict__ Bhi,
    float* __restrict__ rowsum, float* __restrict__ colsum) {
    extern __shared__ char smem[];
    uint32_t sb = smem_u32(smem);
    int tid = threadIdx.x;
    int wid = tid >> 5, lane = tid & 31;
    int by = blockIdx.y;
    int bx0 = blockIdx.x * NCE_CHUNK;
    int bx1 = min(79, bx0 + NCE_CHUNK);
    int warpM = wid >> 1, warpN = wid & 1;
    int lrow = lane & 15, lcol = (lane >> 4) << 4;
    int g = lane >> 2, q = lane & 3;
    bool rowfull = (by < 78);

    int crow[4], ccol[4];
    #pragma unroll
    for (int k = 0; k < 4; k++) {
        int i = tid + k * 256;
        crow[k] = i >> 3;
        ccol[k] = (i & 7) * 16;
    }

    // A tile (resident for whole sweep)
    {
        const uint4* s4 = (const uint4*)(Ahi + by * 128 * 64);
        char* d = smem + NCE_A;
        #pragma unroll
        for (int k = 0; k < 4; k++)
            *(uint4*)(d + crow[k] * NCE_TSTRIDE + ccol[k]) = __ldg(&s4[tid + k * 256]);
    }
    // first B tile: regs -> buf0
    uint4 breg[4];
    {
        const uint4* s4 = (const uint4*)(Bhi + bx0 * 128 * 64);
        #pragma unroll
        for (int k = 0; k < 4; k++) breg[k] = __ldg(&s4[tid + k * 256]);
        char* d = smem + NCE_B0;
        #pragma unroll
        for (int k = 0; k < 4; k++)
            *(uint4*)(d + crow[k] * NCE_TSTRIDE + ccol[k]) = breg[k];
    }
    __syncthreads();

    float rowtot[4] = { 0.f, 0.f, 0.f, 0.f };
    uint32_t aA = sb + NCE_A;
    int cur = 0;

    for (int bx = bx0; bx < bx1; bx++) {
        bool more = (bx + 1 < bx1);
        if (more) {
            const uint4* s4 = (const uint4*)(Bhi + (bx + 1) * 128 * 64);
            #pragma unroll
            for (int k = 0; k < 4; k++) breg[k] = __ldg(&s4[tid + k * 256]);
        }
        uint32_t aB = sb + (cur ? NCE_B1 : NCE_B0);

        float acc[2][8][4];
        #pragma unroll
        for (int mt = 0; mt < 2; mt++)
            #pragma unroll
            for (int nt = 0; nt < 8; nt++)
                #pragma unroll
                for (int d = 0; d < 4; d++) acc[mt][nt][d] = 0.f;

        #pragma unroll
        for (int kk = 0; kk < 4; kk++) {
            int koff = kk * 32 + lcol;
            uint32_t arow = (warpM * 32 + lrow) * NCE_TSTRIDE + koff;
            uint32_t brow = (warpN * 64 + lrow) * NCE_TSTRIDE + koff;
            uint32_t ah[2][4], bh[4][4];
            #pragma unroll
            for (int mt = 0; mt < 2; mt++)
                ldm4(ah[mt], aA + arow + mt * 16 * NCE_TSTRIDE);
            #pragma unroll
            for (int ng2 = 0; ng2 < 4; ng2++)
                ldm4(bh[ng2], aB + brow + ng2 * 16 * NCE_TSTRIDE);
            #pragma unroll
            for (int mt = 0; mt < 2; mt++)
                #pragma unroll
                for (int ng2 = 0; ng2 < 4; ng2++) {
                    mma16816(acc[mt][2 * ng2],     ah[mt], bh[ng2][0], bh[ng2][2]);
                    mma16816(acc[mt][2 * ng2 + 1], ah[mt], bh[ng2][1], bh[ng2][3]);
                }
        }

        float colacc[16];
        #pragma unroll
        for (int i = 0; i < 16; i++) colacc[i] = 0.f;

        if (rowfull && bx < 78) {
            #pragma unroll
            for (int mt = 0; mt < 2; mt++)
                #pragma unroll
                for (int nt = 0; nt < 8; nt++)
                    #pragma unroll
                    for (int d = 0; d < 4; d++) {
                        float e = fexp_logit(acc[mt][nt][d]);
                        rowtot[mt * 2 + (d >> 1)] += e;
                        colacc[nt * 2 + (d & 1)] += e;
                    }
            #pragma unroll
            for (int i = 0; i < 16; i++) {
                float v = colacc[i];
                v += __shfl_xor_sync(0xffffffffu, v, 4);
                v += __shfl_xor_sync(0xffffffffu, v, 8);
                v += __shfl_xor_sync(0xffffffffu, v, 16);
                if (g == 0)
                    atomicAdd(&colsum[bx * 128 + warpN * 64 + (i >> 1) * 8 + 2 * q + (i & 1)], v);
            }
        } else {
            #pragma unroll
            for (int mt = 0; mt < 2; mt++)
                #pragma unroll
                for (int nt = 0; nt < 8; nt++)
                    #pragma unroll
                    for (int d = 0; d < 4; d++) {
                        int rh = d >> 1, pr = d & 1;
                        int gr = by * 128 + warpM * 32 + mt * 16 + g + rh * 8;
                        int gc = bx * 128 + warpN * 64 + nt * 8 + 2 * q + pr;
                        float e = (gr < PP && gc < PP) ? fexp_logit(acc[mt][nt][d]) : 0.f;
                        rowtot[mt * 2 + rh] += e;
                        colacc[nt * 2 + pr] += e;
                    }
            #pragma unroll
            for (int i = 0; i < 16; i++) {
                float v = colacc[i];
                v += __shfl_xor_sync(0xffffffffu, v, 4);
                v += __shfl_xor_sync(0xffffffffu, v, 8);
                v += __shfl_xor_sync(0xffffffffu, v, 16);
                int gc = bx * 128 + warpN * 64 + (i >> 1) * 8 + 2 * q + (i & 1);
                if (g == 0 && gc < PP) atomicAdd(&colsum[gc], v);
            }
        }

        if (more) {
            char* d = smem + (cur ? NCE_B0 : NCE_B1);
            #pragma unroll
            for (int k = 0; k < 4; k++)
                *(uint4*)(d + crow[k] * NCE_TSTRIDE + ccol[k]) = breg[k];
        }
        __syncthreads();
        cur ^= 1;
    }

    #pragma unroll
    for (int r = 0; r < 4; r++) {
        float v = rowtot[r];
        v += __shfl_xor_sync(0xffffffffu, v, 1);
        v += __shfl_xor_sync(0xffffffffu, v, 2);
        int gr = by * 128 + warpM * 32 + (r >> 1) * 16 + g + (r & 1) * 8;
        if (q == 0 && gr < PP) atomicAdd(&rowsum[gr], v);
    }
}

// ---------------- loss reduction (grid-parallel, atomic) ---------------------------
__global__ void loss_kernel(const float* __restrict__ ng, const float* __restrict__ ns,
                            const float* __restrict__ rowsum, const float* __restrict__ colsum,
                            float* __restrict__ out) {
    __shared__ float sred[256];
    float t1 = 0.f;
    for (int i = blockIdx.x * 256 + threadIdx.x; i < PP; i += gridDim.x * 256) {
        const float4* a = (const float4*)&ng[i * 64];
        const float4* b = (const float4*)&ns[i * 64];
        float dot = 0.f;
        #pragma unroll
        for (int k = 0; k < 16; k++) {
            float4 x = __ldg(&a[k]), y = __ldg(&b[k]);
            dot += x.x * y.x + x.y * y.y + x.z * y.z + x.w * y.w;
        }
        float pos = fexp_logit(dot);
        t1 += -logf(pos / (rowsum[i] + 1e-8f) + 1e-8f);
        t1 += -logf(pos / (colsum[i] + 1e-8f) + 1e-8f);
    }
    sred[threadIdx.x] = t1;
    __syncthreads();
    for (int o = 128; o; o >>= 1) {
        if (threadIdx.x < o) sred[threadIdx.x] += sred[threadIdx.x + o];
        __syncthreads();
    }
    if (threadIdx.x == 0) atomicAdd(out, sred[0] * (0.5f / PP));
}

// ---------------- fused message MLP -> hg_users ------------------------------------
#define CST 452
__global__ void msg_kernel(const float* __restrict__ mg, const float* __restrict__ ms,
                           const float* __restrict__ mp, const float* __restrict__ ue,
                           const float* __restrict__ fw, const float* __restrict__ fb,
                           float* __restrict__ hu) {
    extern __shared__ float sm[];
    float4* fws = (float4*)sm;          // 448*16 float4
    float* cs = sm + 28672;             // 32 * CST floats
    int t = threadIdx.x;
    for (int i = t; i < 7168; i += 256) fws[i] = __ldg(&((const float4*)fw)[i]);
    int q = t & 15, ug = t >> 4;
    float4 fb4 = ((const float4*)fb)[q];
    int ubase = blockIdx.x * 32;
    #pragma unroll
    for (int s = 0; s < 2; s++) {
        int u = ubase + ug * 2 + s;
        float* cg = cs + (ug * 2 + s) * CST;
        float4 a = ((const float4*)mg)[u * 16 + q];
        float4 b = ((const float4*)ms)[u * 16 + q];
        float4 c = ((const float4*)mp)[u * 16 + q];
        float4 ab = make_float4(a.x*b.x, a.y*b.y, a.z*b.z, a.w*b.w);
        float4 ac = make_float4(a.x*c.x, a.y*c.y, a.z*c.z, a.w*c.w);
        float4 bc = make_float4(b.x*c.x, b.y*c.y, b.z*c.z, b.w*c.w);
        float4 abc = make_float4(ab.x*c.x, ab.y*c.y, ab.z*c.z, ab.w*c.w);
        *(float4*)&cg[0   + q*4] = a;
        *(float4*)&cg[64  + q*4] = b;
        *(float4*)&cg[128 + q*4] = c;
        *(float4*)&cg[192 + q*4] = ab;
        *(float4*)&cg[256 + q*4] = ac;
        *(float4*)&cg[320 + q*4] = bc;
        *(float4*)&cg[384 + q*4] = abc;
    }
    __syncthreads();
    float4 acc0 = make_float4(0,0,0,0), acc1 = make_float4(0,0,0,0);
    const float* cg0 = cs + (ug * 2) * CST;
    const float* cg1 = cg0 + CST;
    #pragma unroll 4
    for (int i = 0; i < 448; i++) {
        float4 w4 = fws[i * 16 + q];
        float s0 = cg0[i], s1 = cg1[i];
        acc0.x = fmaf(s0, w4.x, acc0.x); acc0.y = fmaf(s0, w4.y, acc0.y);
        acc0.z = fmaf(s0, w4.z, acc0.z); acc0.w = fmaf(s0, w4.w, acc0.w);
        acc1.x = fmaf(s1, w4.x, acc1.x); acc1.y = fmaf(s1, w4.y, acc1.y);
        acc1.z = fmaf(s1, w4.z, acc1.z); acc1.w = fmaf(s1, w4.w, acc1.w);
    }
    #pragma unroll
    for (int s = 0; s < 2; s++) {
        int u = ubase + ug * 2 + s;
        float4 acc = s ? acc1 : acc0;
        float4 me = make_float4(fb4.x + acc.x, fb4.y + acc.y, fb4.z + acc.z, fb4.w + acc.w);
        float4 u4 = ((const float4*)ue)[u * 16 + q];
        float4 r;
        r.x = me.x + u4.x + me.x * u4.x;
        r.y = me.y + u4.y + me.y * u4.y;
        r.z = me.z + u4.z + me.z * u4.z;
        r.w = me.w + u4.w + me.w * u4.w;
        ((float4*)hu)[u * 16 + q] = r;
    }
}

// ---------------- fusion_pois / batch_users ---------------------------------------
__global__ void fusion_kernel(const float* __restrict__ colg, const float* __restrict__ s,
                              const float* __restrict__ ng, const float* __restrict__ ns,
                              float* __restrict__ out) {
    int row = blockIdx.x * 8 + (threadIdx.x >> 5);
    if (row >= PP) return;
    int lane = threadIdx.x & 31;
    int i = row * 32 + lane;
    float2 vc = ((const float2*)colg)[i], vs = ((const float2*)s)[i];
    float vx = vc.x + vs.x, vy = vc.y + vs.y;
    float sq = vx * vx + vy * vy;
    #pragma unroll
    for (int o = 16; o; o >>= 1) sq += __shfl_xor_sync(0xffffffffu, sq, o);
    float inv = 1.f / fmaxf(sqrtf(sq), 1e-12f);
    float2 vg = ((const float2*)ng)[i], vn = ((const float2*)ns)[i];
    ((float2*)out)[i] = make_float2(vx * inv + vg.x + vn.x, vy * inv + vg.y + vn.y);
}

__global__ void batch_kernel(const float* __restrict__ us, const int* __restrict__ uidx,
                             float* __restrict__ out) {
    int b = blockIdx.x * 8 + (threadIdx.x >> 5);
    if (b >= BBATCH) return;
    int lane = threadIdx.x & 31;
    int u = __ldg(&uidx[b]);
    float2 v = ((const float2*)us)[u * 32 + lane];
    float sq = v.x * v.x + v.y * v.y;
    #pragma unroll
    for (int o = 16; o; o >>= 1) sq += __shfl_xor_sync(0xffffffffu, sq, o);
    float inv = 1.f / fmaxf(sqrtf(sq), 1e-12f);
    ((float2*)out)[b * 32 + lane] = make_float2(v.x * inv, v.y * inv);
}

// ---------------- host side --------------------------------------------------------
static void* getsym(const void* shadow) {
    void* p = nullptr;
    cudaGetSymbolAddress(&p, shadow);
    return p;
}

extern "C" void kernel_launch(void* const* d_in, const int* in_sizes, int n_in,
                              void* d_out, int out_size) {
    const float* poi_emb  = (const float*)d_in[0];
    const float* user_emb = (const float*)d_in[1];
    const float* w_geo    = (const float*)d_in[2];
    const float* b_geo    = (const float*)d_in[3];
    const float* w_seq    = (const float*)d_in[4];
    const float* b_seq    = (const float*)d_in[5];
    const float* w_col    = (const float*)d_in[6];
    const float* b_col    = (const float*)d_in[7];
    const float* fusion_w = (const float*)d_in[8];
    const float* fusion_b = (const float*)d_in[9];
    const float* geo_vals = (const float*)d_in[10];
    const float* src_vals = (const float*)d_in[11];
    const float* tar_vals = (const float*)d_in[12];
    const float* up_vals  = (const float*)d_in[13];
    const float* pu_vals  = (const float*)d_in[14];
    const int* geo_rows = (const int*)d_in[15];
    const int* geo_cols = (const int*)d_in[16];
    const int* src_rows = (const int*)d_in[17];
    const int* src_cols = (const int*)d_in[18];
    const int* tar_rows = (const int*)d_in[19];
    const int* tar_cols = (const int*)d_in[20];
    const int* up_rows  = (const int*)d_in[21];
    const int* up_cols  = (const int*)d_in[22];
    const int* pu_rows  = (const int*)d_in[23];
    const int* pu_cols  = (const int*)d_in[24];
    const int* user_idx = (const int*)d_in[25];
    float* out = (float*)d_out;

    float* Ggeo = (float*)getsym(g_Ggeo);
    float* Gseq = (float*)getsym(g_Gseq);
    float* Colg = (float*)getsym(g_Colg);
    float* T1 = (float*)getsym(g_T1);
    float* T3 = (float*)getsym(g_T3);
    float* T4 = (float*)getsym(g_T4);
    float* NGv = (float*)getsym(g_NGb);
    float* NSv = (float*)getsym(g_NSb);
    __nv_bfloat16* NGhi = (__nv_bfloat16*)getsym(g_NGhi);
    __nv_bfloat16* NShi = (__nv_bfloat16*)getsym(g_NShi);
    float* MG = (float*)getsym(g_MG);
    float* MS = (float*)getsym(g_MS);
    float* MP = (float*)getsym(g_MP);
    float* HU = (float*)getsym(g_HU);
    float* US = (float*)getsym(g_US);
    float* rowsum = (float*)getsym(g_rowsum);
    float* colsum = (float*)getsym(g_colsum);
    int* cnt_all = (int*)getsym(g_cnt_all);
    int* cur_all = (int*)getsym(g_cur_all);
    int* ptr_geo = (int*)getsym(g_ptr_geo);
    int* ptr_src = (int*)getsym(g_ptr_src);
    int* ptr_tar = (int*)getsym(g_ptr_tar);
    int* ptr_pu  = (int*)getsym(g_ptr_pu);
    int* ptr_up  = (int*)getsym(g_ptr_up);
    int2* cs_geo = (int2*)getsym(g_cs_geo);
    int2* cs_src = (int2*)getsym(g_cs_src);
    int2* cs_tar = (int2*)getsym(g_cs_tar);
    int2* cs_up  = (int2*)getsym(g_cs_up);
    int2* cs_pu  = (int2*)getsym(g_cs_pu);

    cudaFuncSetAttribute(infonce_mma_kernel, cudaFuncAttributeMaxDynamicSharedMemorySize,
                         NCE_SMEM);
    cudaFuncSetAttribute(msg_kernel, cudaFuncAttributeMaxDynamicSharedMemorySize, 180000);

    // static stream + events: created ONCE on the first (correctness) call.
    static cudaStream_t aux = nullptr;
    static cudaEvent_t evFork, evGates, evGeo, evNS, evTail;
    if (aux == nullptr) {
        cudaStreamCreateWithFlags(&aux, cudaStreamNonBlocking);
        cudaEventCreateWithFlags(&evFork, cudaEventDisableTiming);
        cudaEventCreateWithFlags(&evGates, cudaEventDisableTiming);
        cudaEventCreateWithFlags(&evGeo, cudaEventDisableTiming);
        cudaEventCreateWithFlags(&evNS, cudaEventDisableTiming);
        cudaEventCreateWithFlags(&evTail, cudaEventDisableTiming);
    }

    const int gridPW = (PP + 7) / 8, gridUW = (UU + 7) / 8;
    const int gridPdW = (PPAD + 7) / 8;
    const int gridU16 = (UU + 15) / 16;
    const int gridP8 = (PP + 7) / 8;

    // ---- fork: gates + aux-zero on aux || zero(tar,src) + CSR(tar,src) on main ----
    cudaEventRecord(evFork, 0);
    cudaStreamWaitEvent(aux, evFork, 0);
    gates_kernel<<<(PP + 15) / 16, 256, 0, aux>>>(poi_emb, w_geo, b_geo, w_seq, b_seq,
                                                  w_col, b_col, Ggeo, Gseq, Colg);
    cudaEventRecord(evGates, aux);
    zero_aux_kernel<<<(PP + UU + 255) / 256, 256, 0, aux>>>(cnt_all, rowsum, colsum,
                                                            out + OUT_LOSS);

    zero_main_kernel<<<(2 * PP + 255) / 256, 256>>>(cnt_all);
    dim3 ghh2((NDNZ + 511) / 512, 2);
    hist2_kernel<<<ghh2, 256>>>(tar_rows, src_rows, cnt_all);
    scan2_kernel<<<2, 1024>>>(cnt_all, cur_all, ptr_tar, ptr_src);
    dim3 gs2((NDNZ + 1023) / 1024, 2);
    scatter2_kernel<<<gs2, 256>>>(tar_rows, tar_cols, tar_vals,
                                  src_rows, src_cols, src_vals,
                                  cs_tar, cs_src, cur_all);
    cudaStreamWaitEvent(0, evGates, 0);
    spmm_kernel<<<gridPW, 256>>>(ptr_tar, cs_tar, Gseq, nullptr, T3, PP);
    spmm_kernel<<<gridPW, 256>>>(ptr_src, cs_src, T3, Gseq, T4, PP);
    spmm_kernel<<<gridPW, 256>>>(ptr_tar, cs_tar, T4, nullptr, T3, PP);
    spmm_norm_kernel<<<gridPdW, 256>>>(ptr_src, cs_src, T3, Gseq, T4, NSv, NShi);
    cudaEventRecord(evNS, 0);

    // aux: CSR(geo,up,pu) + geo chain
    dim3 ghh3((NPUNZ + 511) / 512, 3);
    hist3_kernel<<<ghh3, 256, 0, aux>>>(geo_rows, up_rows, pu_rows, cnt_all);
    scan3_kernel<<<3, 1024, 0, aux>>>(cnt_all, cur_all, ptr_geo, ptr_up, ptr_pu);
    dim3 gs3((NPUNZ + 1023) / 1024, 3);
    scatter3_kernel<<<gs3, 256, 0, aux>>>(geo_rows, geo_cols, geo_vals,
                                          up_rows, up_cols, up_vals,
                                          pu_rows, pu_cols, pu_vals,
                                          cs_geo, cs_up, cs_pu, cur_all);
    spmm_kernel<<<gridPW, 256, 0, aux>>>(ptr_geo, cs_geo, Ggeo, Ggeo, T1, PP);
    spmm_norm_kernel<<<gridPdW, 256, 0, aux>>>(ptr_geo, cs_geo, T1, Ggeo, T1, NGv, NGhi);
    cudaEventRecord(evGeo, aux);

    // main: infonce + loss (needs NG from aux)
    cudaStreamWaitEvent(0, evGeo, 0);
    dim3 gnce(8, PPAD / 128);
    infonce_mma_kernel<<<gnce, 256, NCE_SMEM>>>(NGhi, NShi, rowsum, colsum);
    loss_kernel<<<40, 256>>>(NGv, NSv, rowsum, colsum, out + OUT_LOSS);

    // aux: multi-view tail (needs NS from main; geo/up/pu CSR and NG/Colg local)
    cudaStreamWaitEvent(aux, evNS, 0);
    spmm3_kernel<<<gridU16, 256, 0, aux>>>(ptr_up, cs_up, NGv, NSv, Colg, MG, MS, MP, UU);
    msg_kernel<<<250, 256, (28672 + 32 * CST) * sizeof(float), aux>>>(MG, MS, MP, user_emb,
                                                                      fusion_w, fusion_b, HU);
    spmm_kernel<<<gridPW, 256, 0, aux>>>(ptr_pu, cs_pu, HU, nullptr, T1, PP);
    fusion_kernel<<<gridP8, 256, 0, aux>>>(Colg, T1, NGv, NSv, out + OUT_FUS);
    spmm_kernel<<<gridUW, 256, 0, aux>>>(ptr_up, cs_up, out + OUT_FUS, nullptr, US, UU);
    batch_kernel<<<(BBATCH + 7) / 8, 256, 0, aux>>>(US, user_idx, out + OUT_BATCH);
    cudaEventRecord(evTail, aux);
    cudaStreamWaitEvent(0, evTail, 0);
}